// round 1
// baseline (speedup 1.0000x reference)
#include <cuda_runtime.h>
#include <cstdint>

#define MDIM 8192
#define KDIM 8192
#define NDIM 8192

// ---- scratch (device globals; no allocation allowed) ----
#define ROW_TILES 64
__device__ float g_partial[ROW_TILES * KDIM]; // 2 MiB, overwritten each launch
__device__ float g_wcs[KDIM];                 // 32 KiB column-sum of W

// ============================================================
// Kernel 1: partial column sums of W.
// Grid: (KDIM/1024 = 8 col tiles, ROW_TILES = 64 row tiles), 256 threads.
// Each thread owns 4 consecutive columns (float4) over 128 rows.
// Deterministic: exclusive ownership, plain stores.
// ============================================================
__global__ __launch_bounds__(256) void colsum_partial(const float* __restrict__ w) {
    const int col4 = blockIdx.x * 256 + threadIdx.x;     // float4 index within row
    const int rt = blockIdx.y;
    const int rows_per_tile = NDIM / ROW_TILES;          // 128
    const int row0 = rt * rows_per_tile;

    const float4* wp = reinterpret_cast<const float4*>(w) + (size_t)row0 * (KDIM / 4) + col4;

    float4 acc = make_float4(0.f, 0.f, 0.f, 0.f);
    #pragma unroll 8
    for (int r = 0; r < rows_per_tile; ++r) {
        float4 v = __ldg(wp + (size_t)r * (KDIM / 4));
        acc.x += v.x; acc.y += v.y; acc.z += v.z; acc.w += v.w;
    }
    reinterpret_cast<float4*>(g_partial)[(size_t)rt * (KDIM / 4) + col4] = acc;
}

// ============================================================
// Kernel 2: fold the 64 partials -> g_wcs. Tiny (0.5 MiB read).
// ============================================================
__global__ __launch_bounds__(256) void colsum_reduce() {
    const int k = blockIdx.x * 256 + threadIdx.x;        // column index
    float s = 0.f;
    #pragma unroll 8
    for (int rt = 0; rt < ROW_TILES; ++rt)
        s += g_partial[(size_t)rt * KDIM + k];
    g_wcs[k] = s;
}

// ============================================================
// Kernel 3: y[m] = 0.75 * dot(x[m,:], wcs). One block per row.
// wcs (32 KiB) is L2-resident across all 8192 blocks.
// ============================================================
__global__ __launch_bounds__(256) void rowdot(const float* __restrict__ x,
                                              float* __restrict__ y) {
    const int row = blockIdx.x;
    const int tid = threadIdx.x;
    const float4* xp = reinterpret_cast<const float4*>(x) + (size_t)row * (KDIM / 4);
    const float4* wp = reinterpret_cast<const float4*>(g_wcs);

    float4 acc = make_float4(0.f, 0.f, 0.f, 0.f);
    #pragma unroll 8
    for (int i = tid; i < KDIM / 4; i += 256) {
        float4 a = __ldg(xp + i);
        float4 b = wp[i];
        acc.x += a.x * b.x;
        acc.y += a.y * b.y;
        acc.z += a.z * b.z;
        acc.w += a.w * b.w;
    }
    float s = (acc.x + acc.y) + (acc.z + acc.w);

    // warp reduce
    #pragma unroll
    for (int off = 16; off > 0; off >>= 1)
        s += __shfl_xor_sync(0xFFFFFFFFu, s, off);

    __shared__ float red[8];
    if ((tid & 31) == 0) red[tid >> 5] = s;
    __syncthreads();
    if (tid < 8) {
        float t = red[tid];
        #pragma unroll
        for (int off = 4; off > 0; off >>= 1)
            t += __shfl_xor_sync(0xFFu, t, off);
        if (tid == 0) y[row] = 0.75f * t;
    }
}

extern "C" void kernel_launch(void* const* d_in, const int* in_sizes, int n_in,
                              void* d_out, int out_size) {
    const float* x = (const float*)d_in[0];       // [M, K]
    const float* w = (const float*)d_in[1];       // [N, K]
    float* y = (float*)d_out;                     // [M, 1]

    dim3 g1(KDIM / 1024, ROW_TILES);
    colsum_partial<<<g1, 256>>>(w);
    colsum_reduce<<<KDIM / 256, 256>>>();
    rowdot<<<MDIM, 256>>>(x, y);
}

// round 2
// speedup vs baseline: 1.0317x; 1.0317x over previous
#include <cuda_runtime.h>
#include <cstdint>

#define MDIM 8192
#define KDIM 8192
#define NDIM 8192

// ---- scratch (device globals; no allocation allowed) ----
#define ROW_TILES 128
__device__ float g_partial[ROW_TILES * KDIM]; // 4 MiB, overwritten each launch
__device__ float g_wcs[KDIM];                 // 32 KiB column-sum of W

// ============================================================
// Kernel 1: partial column sums of W.
// Grid: (KDIM/1024 = 8 col tiles, ROW_TILES = 128 row tiles), 256 threads.
// 1024 blocks (~6.9/SM) for high occupancy + balanced waves.
// Each thread owns 4 consecutive columns (float4) over 64 rows.
// Deterministic: exclusive ownership, plain stores.
// ============================================================
__global__ __launch_bounds__(256) void colsum_partial(const float* __restrict__ w) {
    const int col4 = blockIdx.x * 256 + threadIdx.x;     // float4 index within row
    const int rt = blockIdx.y;
    const int rows_per_tile = NDIM / ROW_TILES;          // 64
    const int row0 = rt * rows_per_tile;

    const float4* wp = reinterpret_cast<const float4*>(w) + (size_t)row0 * (KDIM / 4) + col4;

    float4 acc = make_float4(0.f, 0.f, 0.f, 0.f);
    #pragma unroll 8
    for (int r = 0; r < rows_per_tile; ++r) {
        float4 v = __ldcs(wp + (size_t)r * (KDIM / 4));  // one-touch: evict-first
        acc.x += v.x; acc.y += v.y; acc.z += v.z; acc.w += v.w;
    }
    reinterpret_cast<float4*>(g_partial)[(size_t)rt * (KDIM / 4) + col4] = acc;
}

// ============================================================
// Kernel 2: fold the 128 partials -> g_wcs. Small (4 MiB read).
// ============================================================
__global__ __launch_bounds__(256) void colsum_reduce() {
    const int k = blockIdx.x * 256 + threadIdx.x;        // column index
    float s = 0.f;
    #pragma unroll 16
    for (int rt = 0; rt < ROW_TILES; ++rt)
        s += g_partial[(size_t)rt * KDIM + k];
    g_wcs[k] = s;
}

// ============================================================
// Kernel 3: y[m] = 0.75 * dot(x[m,:], wcs). One block per row.
// wcs (32 KiB) is L2-resident across all 8192 blocks.
// ============================================================
__global__ __launch_bounds__(256) void rowdot(const float* __restrict__ x,
                                              float* __restrict__ y) {
    const int row = blockIdx.x;
    const int tid = threadIdx.x;
    const float4* xp = reinterpret_cast<const float4*>(x) + (size_t)row * (KDIM / 4);
    const float4* wp = reinterpret_cast<const float4*>(g_wcs);

    float4 acc = make_float4(0.f, 0.f, 0.f, 0.f);
    #pragma unroll 8
    for (int i = tid; i < KDIM / 4; i += 256) {
        float4 a = __ldcs(xp + i);   // one-touch: evict-first
        float4 b = wp[i];            // hot: stays in L2/L1
        acc.x += a.x * b.x;
        acc.y += a.y * b.y;
        acc.z += a.z * b.z;
        acc.w += a.w * b.w;
    }
    float s = (acc.x + acc.y) + (acc.z + acc.w);

    // warp reduce
    #pragma unroll
    for (int off = 16; off > 0; off >>= 1)
        s += __shfl_xor_sync(0xFFFFFFFFu, s, off);

    __shared__ float red[8];
    if ((tid & 31) == 0) red[tid >> 5] = s;
    __syncthreads();
    if (tid < 8) {
        float t = red[tid];
        #pragma unroll
        for (int off = 4; off > 0; off >>= 1)
            t += __shfl_xor_sync(0xFFu, t, off);
        if (tid == 0) y[row] = 0.75f * t;
    }
}

extern "C" void kernel_launch(void* const* d_in, const int* in_sizes, int n_in,
                              void* d_out, int out_size) {
    const float* x = (const float*)d_in[0];       // [M, K]
    const float* w = (const float*)d_in[1];       // [N, K]
    float* y = (float*)d_out;                     // [M, 1]

    dim3 g1(KDIM / 1024, ROW_TILES);
    colsum_partial<<<g1, 256>>>(w);
    colsum_reduce<<<KDIM / 256, 256>>>();
    rowdot<<<MDIM, 256>>>(x, y);
}